// round 11
// baseline (speedup 1.0000x reference)
#include <cuda_runtime.h>

// TimeSeriesWineSNN: 3-layer LIF SNN, T sequential steps, B=4096.
// I=8 -> H1=28 -> H2=8 -> O=4. beta=0.9, thr=1.0 (subtract reset).
// Outputs: mem3, spk3, spk1, spk2, each [T,B,C].
//
// One warp per batch element (4096 warps; occupancy ceiling for this problem).
// L1: lane l = channel l, SCALAR protected tree8 (r8 showed f32x2 packed math
//     is NOT bit-identical to scalar on sm_103a -> banned).
// L2: single combined LUT holds s_u = fadd(rA, rB) of the protected tree28
//     partials, indexed by 7 gathered spike bits; layout [idx7][u][c2] =>
//     word index == lane (mod 32) -> conflict-free LDS.
//     Final combine: 2 commutative xor-shfl hops.
// L3: full tree8 LUT over the 8-bit s2 mask.
//
// PROTECTED NUMERICS (validated r4-r7, rel_err 4.4e-9):
//  * products rounded separately with SCALAR __fmul_rn (no fma, no f32x2)
//  * tree8:  ((p0+p4)+(p2+p6)) + ((p1+p5)+(p3+p7))
//  * tree28: rA=(p_u+p_{u+16})+(p_{u+8}+p_{u+24}), rB=(p_{u+4}+p_{u+20})+p_{u+12},
//            s_u=rA+rB, tot=(s0+s2)+(s1+s3) via xor-shfl (fadd commutative)
//  * epilogue: m = fma(beta, m_prev, dot + b) - s_prev ; s = (m > 1)

constexpr int   Bb  = 4096;
constexpr int   Ii  = 8;
constexpr int   H1  = 28;
constexpr int   H2  = 8;
constexpr int   Oo  = 4;
constexpr float BETA = 0.9f;
constexpr float THR  = 1.0f;

__device__ __forceinline__ float tree8_local(const float* __restrict__ p) {
    float a = __fadd_rn(__fadd_rn(p[0], p[4]), __fadd_rn(p[2], p[6]));
    float b = __fadd_rn(__fadd_rn(p[1], p[5]), __fadd_rn(p[3], p[7]));
    return __fadd_rn(a, b);
}

__global__ void __launch_bounds__(128)
snn_kernel(const float* __restrict__ x,
           const float* __restrict__ W1, const float* __restrict__ b1,
           const float* __restrict__ W2, const float* __restrict__ b2,
           const float* __restrict__ W3, const float* __restrict__ b3,
           float* __restrict__ out_mem3, float* __restrict__ out_spk3,
           float* __restrict__ out_spk1, float* __restrict__ out_spk2,
           int T)
{
    __shared__ float lut2[128 * 4 * 8];   // [idx7][u][c2] = s_u partial (16 KB)
    __shared__ float lut3[256 * 4];       // [idx8][c3]    = full tree8 (4 KB)

    const int tix = threadIdx.x;

    // ---- build combined L2 LUT (exact protected order, +0 for masked) ----
    for (int e = tix; e < 128 * 4 * 8; e += 128) {
        const int idx7 = e >> 5, u = (e >> 3) & 3, c = e & 7;
        const int idxA = idx7 & 15, idxB = idx7 >> 4;
        const float* row = W2 + c * H1;
        const float pa = (idxA & 1) ? row[u]      : 0.0f;
        const float pb = (idxA & 2) ? row[u + 8]  : 0.0f;
        const float pc = (idxA & 4) ? row[u + 16] : 0.0f;
        const float pd = (idxA & 8) ? row[u + 24] : 0.0f;
        const float qa = (idxB & 1) ? row[u + 4]  : 0.0f;
        const float qb = (idxB & 2) ? row[u + 12] : 0.0f;
        const float qc = (idxB & 4) ? row[u + 20] : 0.0f;
        const float rA = __fadd_rn(__fadd_rn(pa, pc), __fadd_rn(pb, pd));
        const float rB = __fadd_rn(__fadd_rn(qa, qc), qb);
        lut2[e] = __fadd_rn(rA, rB);
    }
    for (int e = tix; e < 256 * 4; e += 128) {
        const int idx = e >> 2, c = e & 3;
        const float* row = W3 + c * H2;
        float p[8];
        #pragma unroll
        for (int k = 0; k < 8; ++k) p[k] = ((idx >> k) & 1) ? row[k] : 0.0f;
        lut3[e] = tree8_local(p);
    }
    __syncthreads();

    const int l = tix & 31;                               // lane
    const int b = (blockIdx.x * blockDim.x + tix) >> 5;   // batch element
    if (b >= Bb) return;

    // ---- layer-1 weights: lane l = channel l (pad >=28 with 0) ----
    float w1r[8], b1r;
    {
        const bool real = (l < H1);
        b1r = real ? b1[l] : 0.0f;
        #pragma unroll
        for (int k = 0; k < Ii; ++k)
            w1r[k] = real ? W1[l * Ii + k] : 0.0f;
    }
    const int c2 = l & 7;
    const int u  = l >> 3;          // 0..3
    const float b2r = b2[c2];
    const int c3 = u;               // 0..3
    const int k3 = l & 7;
    const float b3r = b3[c3];

    const float* lut2l = lut2 + l;          // + idx7*32 at runtime
    const float* lut3c = lut3 + c3;         // + idx8*4  at runtime

    // ---- state ----
    float m1 = 0.f, s1f = 0.f;
    float m2 = 0.f, s2f = 0.f;
    float m3 = 0.f, s3f = 0.f;

    // ---- pointers ----
    const size_t sX  = (size_t)Bb * Ii;
    const size_t st1 = (size_t)Bb * H1;
    const size_t st2 = (size_t)Bb * H2;
    const size_t st3 = (size_t)Bb * Oo;

    const float* px = x + (size_t)b * Ii;
    float* p1 = out_spk1 + (size_t)b * H1 + l;
    float* p2 = out_spk2 + (size_t)b * H2 + c2;
    float* p3 = out_spk3 + (size_t)b * Oo + c3;
    float* pm = out_mem3 + (size_t)b * Oo + c3;

    const bool w1valid = (l < H1);
    const bool w2store = (u == 0);
    const bool w3store = (k3 == 0);

    // prefetch x[t=0] (uniform address across warp -> broadcast)
    float4 xa = *(const float4*)px;
    float4 xb = *(const float4*)(px + 4);

    #pragma unroll 4
    for (int t = 0; t < T; ++t) {
        const float* pn = px + ((t + 1 < T) ? sX : 0);
        const float4 nxa = *(const float4*)pn;
        const float4 nxb = *(const float4*)(pn + 4);
        px = pn;

        const float xk[8] = {xa.x, xa.y, xa.z, xa.w, xb.x, xb.y, xb.z, xb.w};

        // ---------- layer 1 : scalar protected tree8 ----------
        bool sp1;
        {
            float pr[8];
            #pragma unroll
            for (int k = 0; k < Ii; ++k) pr[k] = __fmul_rn(xk[k], w1r[k]);
            float a = __fadd_rn(tree8_local(pr), b1r);
            m1  = __fsub_rn(__fmaf_rn(BETA, m1, a), s1f);
            sp1 = (m1 > THR);
            s1f = sp1 ? 1.0f : 0.0f;
        }
        if (w1valid) *p1 = s1f;

        const unsigned bt = __ballot_sync(0xffffffffu, sp1);  // bit l = s1[l]

        // ---------- layer 2 : combined LUT + 2 commutative xor hops ----------
        bool sp2;
        {
            const unsigned idxA = (((bt >> u) & 0x01010101u) * 0x01020408u) >> 24;
            const unsigned idxB = (((bt >> (u + 4)) & 0x00010101u) * 0x01020408u) >> 24;
            const unsigned idx7 = idxA + (idxB << 4);
            float s  = lut2l[idx7 * 32];                        // s_u (conflict-free)
            float h  = __fadd_rn(s, __shfl_xor_sync(0xffffffffu, s, 16));
            float tot= __fadd_rn(h, __shfl_xor_sync(0xffffffffu, h, 8));
            float a  = __fadd_rn(tot, b2r);
            m2  = __fsub_rn(__fmaf_rn(BETA, m2, a), s2f);
            sp2 = (m2 > THR);
            s2f = sp2 ? 1.0f : 0.0f;
        }
        if (w2store) *p2 = s2f;

        const unsigned bt2 = __ballot_sync(0xffffffffu, sp2);  // bits 0-7 = s2

        // ---------- layer 3 : single LUT lookup ----------
        {
            const unsigned idx = bt2 & 0xffu;
            float a = __fadd_rn(lut3c[idx * 4], b3r);
            m3  = __fsub_rn(__fmaf_rn(BETA, m3, a), s3f);
            s3f = (m3 > THR) ? 1.0f : 0.0f;
        }
        if (w3store) {
            *p3 = s3f;
            *pm = m3;
        }

        p1 += st1; p2 += st2; p3 += st3; pm += st3;
        xa = nxa; xb = nxb;
    }
}

extern "C" void kernel_launch(void* const* d_in, const int* in_sizes, int n_in,
                              void* d_out, int out_size)
{
    const float* x  = (const float*)d_in[0];
    const float* W1 = (const float*)d_in[1];
    const float* b1 = (const float*)d_in[2];
    const float* W2 = (const float*)d_in[3];
    const float* b2 = (const float*)d_in[4];
    const float* W3 = (const float*)d_in[5];
    const float* b3 = (const float*)d_in[6];

    const int T = in_sizes[0] / (Bb * Ii);
    const size_t TB = (size_t)T * Bb;

    float* out      = (float*)d_out;
    float* out_mem3 = out;
    float* out_spk3 = out + TB * Oo;
    float* out_spk1 = out + 2 * TB * Oo;
    float* out_spk2 = out + 2 * TB * Oo + TB * H1;

    const int threads = Bb * 32;          // one warp per element
    const int block   = 128;
    snn_kernel<<<threads / block, block>>>(x, W1, b1, W2, b2, W3, b3,
                                           out_mem3, out_spk3, out_spk1, out_spk2,
                                           T);
}

// round 13
// speedup vs baseline: 1.4155x; 1.4155x over previous
#include <cuda_runtime.h>

// TimeSeriesWineSNN: 3-layer LIF SNN, T sequential steps, B=4096.
// I=8 -> H1=28 -> H2=8 -> O=4. beta=0.9, thr=1.0 (subtract reset).
// Outputs: mem3, spk3, spk1, spk2, each [T,B,C].
//
// One warp per batch element (4096 warps; grid-limited occupancy ceiling).
// L1: lane l = channel l, SCALAR protected tree8 (f32x2 packed math is NOT
//     bit-identical on sm_103a -> banned, r8).
// L2: TWO independent LUTs (r11 showed merging them serializes the chain and
//     regresses): lutA[u][idx4][c2] = rA, lutB[u][idx3][c2] = rB; the two LDS
//     issue independently and overlap; s_u = fadd(LDS_A, LDS_B).
//     Final combine: 2 commutative xor-shfl hops (16, 8).
// L3: full tree8 LUT over the 8-bit s2 mask.
// Unroll 8 + launch_bounds(128,7): wide ILP window, regs capped to keep
//     7 blocks/SM resident.
//
// PROTECTED NUMERICS (validated r4-r7, rel_err 4.4e-9):
//  * products rounded separately with SCALAR __fmul_rn (no fma, no f32x2)
//  * tree8:  ((p0+p4)+(p2+p6)) + ((p1+p5)+(p3+p7))
//  * tree28: rA=(p_u+p_{u+16})+(p_{u+8}+p_{u+24}), rB=(p_{u+4}+p_{u+20})+p_{u+12},
//            s_u=rA+rB, tot=(s0+s2)+(s1+s3) via xor-shfl (fadd commutative)
//  * epilogue: m = fma(beta, m_prev, dot + b) - s_prev ; s = (m > 1)

constexpr int   Bb  = 4096;
constexpr int   Ii  = 8;
constexpr int   H1  = 28;
constexpr int   H2  = 8;
constexpr int   Oo  = 4;
constexpr float BETA = 0.9f;
constexpr float THR  = 1.0f;

__device__ __forceinline__ float tree8_local(const float* __restrict__ p) {
    float a = __fadd_rn(__fadd_rn(p[0], p[4]), __fadd_rn(p[2], p[6]));
    float b = __fadd_rn(__fadd_rn(p[1], p[5]), __fadd_rn(p[3], p[7]));
    return __fadd_rn(a, b);
}

__global__ void __launch_bounds__(128, 7)
snn_kernel(const float* __restrict__ x,
           const float* __restrict__ W1, const float* __restrict__ b1,
           const float* __restrict__ W2, const float* __restrict__ b2,
           const float* __restrict__ W3, const float* __restrict__ b3,
           float* __restrict__ out_mem3, float* __restrict__ out_spk3,
           float* __restrict__ out_spk1, float* __restrict__ out_spk2,
           int T)
{
    __shared__ float lutA[4 * 16 * 8];   // [u][idx4][c2] = rA partial (2 KB)
    __shared__ float lutB[4 * 8 * 8];    // [u][idx3][c2] = rB partial (1 KB)
    __shared__ float lut3[256 * 4];      // [idx8][c3]    = full tree8 (4 KB)

    const int tix = threadIdx.x;

    // ---- build LUTs (exact protected tree orders; +0 for masked-out) ----
    for (int e = tix; e < 4 * 16 * 8; e += 128) {        // LUTA
        const int uu = e >> 7, idx = (e >> 3) & 15, c = e & 7;
        const float* row = W2 + c * H1;
        const float pa = (idx & 1) ? row[uu]      : 0.0f;
        const float pb = (idx & 2) ? row[uu + 8]  : 0.0f;
        const float pc = (idx & 4) ? row[uu + 16] : 0.0f;
        const float pd = (idx & 8) ? row[uu + 24] : 0.0f;
        lutA[e] = __fadd_rn(__fadd_rn(pa, pc), __fadd_rn(pb, pd));
    }
    for (int e = tix; e < 4 * 8 * 8; e += 128) {         // LUTB
        const int uu = e >> 6, idx = (e >> 3) & 7, c = e & 7;
        const float* row = W2 + c * H1;
        const float pa = (idx & 1) ? row[uu + 4]  : 0.0f;
        const float pb = (idx & 2) ? row[uu + 12] : 0.0f;
        const float pc = (idx & 4) ? row[uu + 20] : 0.0f;
        lutB[e] = __fadd_rn(__fadd_rn(pa, pc), pb);
    }
    for (int e = tix; e < 256 * 4; e += 128) {           // LUT3
        const int idx = e >> 2, c = e & 3;
        const float* row = W3 + c * H2;
        float p[8];
        #pragma unroll
        for (int k = 0; k < 8; ++k) p[k] = ((idx >> k) & 1) ? row[k] : 0.0f;
        lut3[e] = tree8_local(p);
    }
    __syncthreads();

    const int l = tix & 31;                               // lane
    const int b = (blockIdx.x * blockDim.x + tix) >> 5;   // batch element

    // ---- layer-1 weights: lane l = channel l (pad >=28 with 0) ----
    float w1r[8], b1r;
    {
        const bool real = (l < H1);
        b1r = real ? b1[l] : 0.0f;
        #pragma unroll
        for (int k = 0; k < Ii; ++k)
            w1r[k] = real ? W1[l * Ii + k] : 0.0f;
    }
    const int c2 = l & 7;
    const int u  = l >> 3;          // 0..3
    const float b2r = b2[c2];
    const int c3 = u;               // 0..3
    const int k3 = l & 7;
    const float b3r = b3[c3];

    const float* lutAu = lutA + u * (16 * 8) + c2;   // + idxA*8 at runtime
    const float* lutBu = lutB + u * (8 * 8) + c2;    // + idxB*8 at runtime
    const float* lut3c = lut3 + c3;                  // + idx8*4 at runtime

    // ---- state ----
    float m1 = 0.f, s1f = 0.f;
    float m2 = 0.f, s2f = 0.f;
    float m3 = 0.f, s3f = 0.f;

    // ---- pointers ----
    const size_t sX  = (size_t)Bb * Ii;
    const size_t st1 = (size_t)Bb * H1;
    const size_t st2 = (size_t)Bb * H2;
    const size_t st3 = (size_t)Bb * Oo;

    const float* px = x + (size_t)b * Ii;
    float* p1 = out_spk1 + (size_t)b * H1 + l;
    float* p2 = out_spk2 + (size_t)b * H2 + c2;
    float* p3 = out_spk3 + (size_t)b * Oo + c3;
    float* pm = out_mem3 + (size_t)b * Oo + c3;

    const bool w1valid = (l < H1);
    const bool w2store = (u == 0);
    const bool w3store = (k3 == 0);

    // prefetch x[t=0] (uniform address across warp -> broadcast)
    float4 xa = *(const float4*)px;
    float4 xb = *(const float4*)(px + 4);

    #pragma unroll 8
    for (int t = 0; t < T; ++t) {
        const float* pn = px + ((t + 1 < T) ? sX : 0);
        const float4 nxa = *(const float4*)pn;
        const float4 nxb = *(const float4*)(pn + 4);
        px = pn;

        const float xk[8] = {xa.x, xa.y, xa.z, xa.w, xb.x, xb.y, xb.z, xb.w};

        // ---------- layer 1 : scalar protected tree8 ----------
        bool sp1;
        {
            float pr[8];
            #pragma unroll
            for (int k = 0; k < Ii; ++k) pr[k] = __fmul_rn(xk[k], w1r[k]);
            float a = __fadd_rn(tree8_local(pr), b1r);
            m1  = __fsub_rn(__fmaf_rn(BETA, m1, a), s1f);
            sp1 = (m1 > THR);
            s1f = sp1 ? 1.0f : 0.0f;
        }
        if (w1valid) *p1 = s1f;

        const unsigned bt = __ballot_sync(0xffffffffu, sp1);  // bit l = s1[l]

        // ---------- layer 2 : two independent LUT loads + 2 xor hops ----------
        bool sp2;
        {
            const unsigned btu  = bt >> u;
            const unsigned idxA = ((btu & 0x01010101u) * 0x01020408u) >> 24;
            const unsigned idxB = (((btu >> 4) & 0x00010101u) * 0x01020408u) >> 24;
            float rA = lutAu[idxA * 8];                        // independent LDS
            float rB = lutBu[idxB * 8];                        // independent LDS
            float s  = __fadd_rn(rA, rB);                      // s_u
            float h  = __fadd_rn(s, __shfl_xor_sync(0xffffffffu, s, 16));
            float tot= __fadd_rn(h, __shfl_xor_sync(0xffffffffu, h, 8));
            float a  = __fadd_rn(tot, b2r);
            m2  = __fsub_rn(__fmaf_rn(BETA, m2, a), s2f);
            sp2 = (m2 > THR);
            s2f = sp2 ? 1.0f : 0.0f;
        }
        if (w2store) *p2 = s2f;

        const unsigned bt2 = __ballot_sync(0xffffffffu, sp2);  // bits 0-7 = s2

        // ---------- layer 3 : single LUT lookup ----------
        {
            const unsigned idx = bt2 & 0xffu;
            float a = __fadd_rn(lut3c[idx * 4], b3r);
            m3  = __fsub_rn(__fmaf_rn(BETA, m3, a), s3f);
            s3f = (m3 > THR) ? 1.0f : 0.0f;
        }
        if (w3store) {
            *p3 = s3f;
            *pm = m3;
        }

        p1 += st1; p2 += st2; p3 += st3; pm += st3;
        xa = nxa; xb = nxb;
    }
}

extern "C" void kernel_launch(void* const* d_in, const int* in_sizes, int n_in,
                              void* d_out, int out_size)
{
    const float* x  = (const float*)d_in[0];
    const float* W1 = (const float*)d_in[1];
    const float* b1 = (const float*)d_in[2];
    const float* W2 = (const float*)d_in[3];
    const float* b2 = (const float*)d_in[4];
    const float* W3 = (const float*)d_in[5];
    const float* b3 = (const float*)d_in[6];

    const int T = in_sizes[0] / (Bb * Ii);
    const size_t TB = (size_t)T * Bb;

    float* out      = (float*)d_out;
    float* out_mem3 = out;
    float* out_spk3 = out + TB * Oo;
    float* out_spk1 = out + 2 * TB * Oo;
    float* out_spk2 = out + 2 * TB * Oo + TB * H1;

    const int threads = Bb * 32;          // one warp per element
    const int block   = 128;
    snn_kernel<<<threads / block, block>>>(x, W1, b1, W2, b2, W3, b3,
                                           out_mem3, out_spk3, out_spk1, out_spk2,
                                           T);
}

// round 14
// speedup vs baseline: 1.4644x; 1.0345x over previous
#include <cuda_runtime.h>

// TimeSeriesWineSNN: 3-layer LIF SNN, T sequential steps, B=4096.
// I=8 -> H1=28 -> H2=8 -> O=4. beta=0.9, thr=1.0 (subtract reset).
// Outputs: mem3, spk3, spk1, spk2, each [T,B,C].
//
// One warp per batch element (4096 warps; grid-limited occupancy ceiling).
// L1: lane l = channel l, SCALAR protected tree8 (f32x2 NOT bit-identical on
//     sm_103a -> banned, r8).
// L2: TWO independent LUTs (merging serializes & regresses, r11):
//     lutA[u][idx4][c2]=rA, lutB[u][idx3][c2]=rB; s_u = fadd(LDS_A, LDS_B);
//     combine via 2 commutative xor-shfl hops (16, 8).
// L3: full tree8 LUT over the 8-bit s2 mask.
// Time loop: 8-step unrolled CHUNKS with immediate-offset x prefetch
//     (independent LDG addresses -> high MLP), clamp peeled into a tail loop.
// launch_bounds(128,7) caps regs to keep 7 blocks/SM resident.
//
// PROTECTED NUMERICS (validated r4-r13, rel_err 4.402054e-9):
//  * products rounded separately with SCALAR __fmul_rn (no fma, no f32x2)
//  * tree8:  ((p0+p4)+(p2+p6)) + ((p1+p5)+(p3+p7))
//  * tree28: rA=(p_u+p_{u+16})+(p_{u+8}+p_{u+24}), rB=(p_{u+4}+p_{u+20})+p_{u+12},
//            s_u=rA+rB, tot=(s0+s2)+(s1+s3) via xor-shfl (fadd commutative)
//  * epilogue: m = fma(beta, m_prev, dot + b) - s_prev ; s = (m > 1)

constexpr int   Bb  = 4096;
constexpr int   Ii  = 8;
constexpr int   H1  = 28;
constexpr int   H2  = 8;
constexpr int   Oo  = 4;
constexpr float BETA = 0.9f;
constexpr float THR  = 1.0f;

__device__ __forceinline__ float tree8_local(const float* __restrict__ p) {
    float a = __fadd_rn(__fadd_rn(p[0], p[4]), __fadd_rn(p[2], p[6]));
    float b = __fadd_rn(__fadd_rn(p[1], p[5]), __fadd_rn(p[3], p[7]));
    return __fadd_rn(a, b);
}

__global__ void __launch_bounds__(128, 7)
snn_kernel(const float* __restrict__ x,
           const float* __restrict__ W1, const float* __restrict__ b1,
           const float* __restrict__ W2, const float* __restrict__ b2,
           const float* __restrict__ W3, const float* __restrict__ b3,
           float* __restrict__ out_mem3, float* __restrict__ out_spk3,
           float* __restrict__ out_spk1, float* __restrict__ out_spk2,
           int T)
{
    __shared__ float lutA[4 * 16 * 8];   // [u][idx4][c2] = rA partial (2 KB)
    __shared__ float lutB[4 * 8 * 8];    // [u][idx3][c2] = rB partial (1 KB)
    __shared__ float lut3[256 * 4];      // [idx8][c3]    = full tree8 (4 KB)

    const int tix = threadIdx.x;

    // ---- build LUTs (exact protected tree orders; +0 for masked-out) ----
    for (int e = tix; e < 4 * 16 * 8; e += 128) {        // LUTA
        const int uu = e >> 7, idx = (e >> 3) & 15, c = e & 7;
        const float* row = W2 + c * H1;
        const float pa = (idx & 1) ? row[uu]      : 0.0f;
        const float pb = (idx & 2) ? row[uu + 8]  : 0.0f;
        const float pc = (idx & 4) ? row[uu + 16] : 0.0f;
        const float pd = (idx & 8) ? row[uu + 24] : 0.0f;
        lutA[e] = __fadd_rn(__fadd_rn(pa, pc), __fadd_rn(pb, pd));
    }
    for (int e = tix; e < 4 * 8 * 8; e += 128) {         // LUTB
        const int uu = e >> 6, idx = (e >> 3) & 7, c = e & 7;
        const float* row = W2 + c * H1;
        const float pa = (idx & 1) ? row[uu + 4]  : 0.0f;
        const float pb = (idx & 2) ? row[uu + 12] : 0.0f;
        const float pc = (idx & 4) ? row[uu + 20] : 0.0f;
        lutB[e] = __fadd_rn(__fadd_rn(pa, pc), pb);
    }
    for (int e = tix; e < 256 * 4; e += 128) {           // LUT3
        const int idx = e >> 2, c = e & 3;
        const float* row = W3 + c * H2;
        float p[8];
        #pragma unroll
        for (int k = 0; k < 8; ++k) p[k] = ((idx >> k) & 1) ? row[k] : 0.0f;
        lut3[e] = tree8_local(p);
    }
    __syncthreads();

    const int l = tix & 31;                               // lane
    const int b = (blockIdx.x * blockDim.x + tix) >> 5;   // batch element

    // ---- layer-1 weights: lane l = channel l (pad >=28 with 0) ----
    float w1r[8], b1r;
    {
        const bool real = (l < H1);
        b1r = real ? b1[l] : 0.0f;
        #pragma unroll
        for (int k = 0; k < Ii; ++k)
            w1r[k] = real ? W1[l * Ii + k] : 0.0f;
    }
    const int c2 = l & 7;
    const int u  = l >> 3;          // 0..3
    const float b2r = b2[c2];
    const int c3 = u;               // 0..3
    const int k3 = l & 7;
    const float b3r = b3[c3];

    const float* lutAu = lutA + u * (16 * 8) + c2;   // + idxA*8 at runtime
    const float* lutBu = lutB + u * (8 * 8) + c2;    // + idxB*8 at runtime
    const float* lut3c = lut3 + c3;                  // + idx8*4 at runtime

    // ---- state ----
    float m1 = 0.f, s1f = 0.f;
    float m2 = 0.f, s2f = 0.f;
    float m3 = 0.f, s3f = 0.f;

    // ---- pointers ----
    const size_t sX  = (size_t)Bb * Ii;
    const size_t st1 = (size_t)Bb * H1;
    const size_t st2 = (size_t)Bb * H2;
    const size_t st3 = (size_t)Bb * Oo;

    const float* xrow = x + (size_t)b * Ii;
    float* p1 = out_spk1 + (size_t)b * H1 + l;
    float* p2 = out_spk2 + (size_t)b * H2 + c2;
    float* p3 = out_spk3 + (size_t)b * Oo + c3;
    float* pm = out_mem3 + (size_t)b * Oo + c3;

    const bool w1valid = (l < H1);
    const bool w2store = (u == 0);
    const bool w3store = (k3 == 0);

    // current-step x (t=0)
    float4 xa = *(const float4*)xrow;
    float4 xb = *(const float4*)(xrow + 4);

    // one full LIF step on (xa, xb); advances output pointers.
    auto step = [&]() {
        const float xk[8] = {xa.x, xa.y, xa.z, xa.w, xb.x, xb.y, xb.z, xb.w};

        // ---------- layer 1 : scalar protected tree8 ----------
        bool sp1;
        {
            float pr[8];
            #pragma unroll
            for (int k = 0; k < Ii; ++k) pr[k] = __fmul_rn(xk[k], w1r[k]);
            float a = __fadd_rn(tree8_local(pr), b1r);
            m1  = __fsub_rn(__fmaf_rn(BETA, m1, a), s1f);
            sp1 = (m1 > THR);
            s1f = sp1 ? 1.0f : 0.0f;
        }
        if (w1valid) *p1 = s1f;

        const unsigned bt = __ballot_sync(0xffffffffu, sp1);  // bit l = s1[l]

        // ---------- layer 2 : two independent LUT loads + 2 xor hops ----------
        bool sp2;
        {
            const unsigned btu  = bt >> u;
            const unsigned idxA = ((btu & 0x01010101u) * 0x01020408u) >> 24;
            const unsigned idxB = (((btu >> 4) & 0x00010101u) * 0x01020408u) >> 24;
            float rA = lutAu[idxA * 8];                        // independent LDS
            float rB = lutBu[idxB * 8];                        // independent LDS
            float s  = __fadd_rn(rA, rB);                      // s_u
            float h  = __fadd_rn(s, __shfl_xor_sync(0xffffffffu, s, 16));
            float tot= __fadd_rn(h, __shfl_xor_sync(0xffffffffu, h, 8));
            float a  = __fadd_rn(tot, b2r);
            m2  = __fsub_rn(__fmaf_rn(BETA, m2, a), s2f);
            sp2 = (m2 > THR);
            s2f = sp2 ? 1.0f : 0.0f;
        }
        if (w2store) *p2 = s2f;

        const unsigned bt2 = __ballot_sync(0xffffffffu, sp2);  // bits 0-7 = s2

        // ---------- layer 3 : single LUT lookup ----------
        {
            const unsigned idx = bt2 & 0xffu;
            float a = __fadd_rn(lut3c[idx * 4], b3r);
            m3  = __fsub_rn(__fmaf_rn(BETA, m3, a), s3f);
            s3f = (m3 > THR) ? 1.0f : 0.0f;
        }
        if (w3store) {
            *p3 = s3f;
            *pm = m3;
        }

        p1 += st1; p2 += st2; p3 += st3; pm += st3;
    };

    // ---- main: 8-step chunks, unconditional prefetch (t+1 <= tmain < T) ----
    const int tmain = (T >= 8) ? ((T - 1) & ~7) : 0;
    for (int tb = 0; tb < tmain; tb += 8) {
        #pragma unroll
        for (int i = 0; i < 8; ++i) {
            // independent address: chunk base + immediate (i+1)*sX
            const float* pn = xrow + (size_t)(tb + i + 1) * sX;
            const float4 nxa = *(const float4*)pn;
            const float4 nxb = *(const float4*)(pn + 4);
            step();
            xa = nxa; xb = nxb;
        }
    }

    // ---- tail: clamped prefetch (1..8 steps) ----
    for (int t = tmain; t < T; ++t) {
        const int tn = (t + 1 < T) ? (t + 1) : t;
        const float* pn = xrow + (size_t)tn * sX;
        const float4 nxa = *(const float4*)pn;
        const float4 nxb = *(const float4*)(pn + 4);
        step();
        xa = nxa; xb = nxb;
    }
}

extern "C" void kernel_launch(void* const* d_in, const int* in_sizes, int n_in,
                              void* d_out, int out_size)
{
    const float* x  = (const float*)d_in[0];
    const float* W1 = (const float*)d_in[1];
    const float* b1 = (const float*)d_in[2];
    const float* W2 = (const float*)d_in[3];
    const float* b2 = (const float*)d_in[4];
    const float* W3 = (const float*)d_in[5];
    const float* b3 = (const float*)d_in[6];

    const int T = in_sizes[0] / (Bb * Ii);
    const size_t TB = (size_t)T * Bb;

    float* out      = (float*)d_out;
    float* out_mem3 = out;
    float* out_spk3 = out + TB * Oo;
    float* out_spk1 = out + 2 * TB * Oo;
    float* out_spk2 = out + 2 * TB * Oo + TB * H1;

    const int threads = Bb * 32;          // one warp per element
    const int block   = 128;
    snn_kernel<<<threads / block, block>>>(x, W1, b1, W2, b2, W3, b3,
                                           out_mem3, out_spk3, out_spk1, out_spk2,
                                           T);
}